// round 6
// baseline (speedup 1.0000x reference)
#include <cuda_runtime.h>
#include <math.h>

#define NB   256            // graphs
#define NRr  268            // ROIs per graph
#define NT   (NB*NRr)       // total nodes = 68608
#define IC   256
#define OC   64
#define NCm  7
#define DEG  32
#define EPG  (NRr*DEG)      // edges per graph = 8576
#define ET   (NT*DEG)       // total edges = 2195456
#define KK   214            // top-k per graph
#define QT   256            // sigmoid table resolution
#define LN_EPS 1e-5f
#define CHUNK (EPG/8)       // 1072 edges per warp in k_csr

// output layout (float32, concatenated in reference return order)
#define XP_OFF   0
#define BAT_OFF  (NB*KK*OC)                 // 3506176
#define SC_OFF   (BAT_OFF + NB*KK)          // 3560960
#define PERM_OFF (SC_OFF + NT)              // 3629568

// ---------------- scratch (device globals; no allocation allowed) ----------
__device__ float g_cw[NRr*NCm];
__device__ float g_tab[(QT+1)*OC];          // sigmoid(ea*w[c]+b[c]) table, row QT = self-loop gate
__device__ float g_roik[NRr*IC*OC];         // 17.6 MB
__device__ float g_xt[NT*OC];               // xt (per-node transform result)
__device__ float g_out[NT*OC];              // h after fused conv+ELU+LN
__device__ unsigned short g_bsrc[ET];       // CSR bucket: LOCAL src node per slot
__device__ float g_bea[ET];                 // CSR bucket: edge_attr per slot
__device__ int   g_off[NT+1];               // CSR offsets (global edge space)

// ---------------- kernels --------------------------------------------------
__global__ void k_cw(const float* __restrict__ rc) {
    int r = threadIdx.x;
    if (r >= NRr) return;
    double v[NCm]; double m = -1e300;
    #pragma unroll
    for (int c = 0; c < NCm; c++) { v[c] = (double)rc[r*NCm + c]; if (v[c] > m) m = v[c]; }
    double s = 0.0;
    #pragma unroll
    for (int c = 0; c < NCm; c++) { v[c] = exp(v[c] - m); s += v[c]; }
    #pragma unroll
    for (int c = 0; c < NCm; c++) g_cw[r*NCm + c] = (float)(v[c] / s);
}

__global__ void k_tab(const float* __restrict__ w, const float* __restrict__ b) {
    int q = blockIdx.x, c = threadIdx.x;
    double x = ((double)q / (double)QT) * (double)w[c] + (double)b[c];
    g_tab[q*OC + c] = (float)(1.0 / (1.0 + exp(-x)));
}

__global__ void k_roik(const float* __restrict__ basis) {
    int r = blockIdx.x;
    float cwv[NCm];
    #pragma unroll
    for (int c = 0; c < NCm; c++) cwv[c] = g_cw[r*NCm + c];
    const float4* b4 = (const float4*)basis;
    float4* o4 = (float4*)(g_roik + (size_t)r*IC*OC);
    for (int idx = threadIdx.x; idx < IC*OC/4; idx += 256) {
        float4 acc = make_float4(0.f,0.f,0.f,0.f);
        #pragma unroll
        for (int c = 0; c < NCm; c++) {
            float4 t = b4[c*(IC*OC/4) + idx];
            acc.x += cwv[c]*t.x; acc.y += cwv[c]*t.y;
            acc.z += cwv[c]*t.z; acc.w += cwv[c]*t.w;
        }
        o4[idx] = acc;
    }
}

// grouped GEMM: block = ROI r, thread = graph g. xt[g*NRr+r,:] = x[row,:] @ roik[r]
__global__ void __launch_bounds__(256) k_xt(const float* __restrict__ x) {
    __shared__ float Ws[64*OC];             // 16 KB K-tile of W
    int r = blockIdx.x, g = threadIdx.x;
    float4 acc[16];
    #pragma unroll
    for (int i = 0; i < 16; i++) acc[i] = make_float4(0.f,0.f,0.f,0.f);
    const float* xrow = x + ((size_t)(g*NRr + r))*IC;
    for (int kt = 0; kt < 4; kt++) {
        __syncthreads();
        const float4* src = (const float4*)(g_roik + (size_t)r*IC*OC + (size_t)kt*64*OC);
        float4* dst = (float4*)Ws;
        for (int i = threadIdx.x; i < 64*OC/4; i += 256) dst[i] = src[i];
        __syncthreads();
        const float4* xr4 = (const float4*)(xrow + kt*64);
        for (int k4 = 0; k4 < 16; k4++) {
            float4 xv = xr4[k4];
            #pragma unroll
            for (int kk = 0; kk < 4; kk++) {
                float xs = (&xv.x)[kk];
                const float4* wrow = (const float4*)(Ws + (k4*4 + kk)*OC);
                #pragma unroll
                for (int o4 = 0; o4 < 16; o4++) {
                    float4 w = wrow[o4];
                    acc[o4].x += xs*w.x; acc[o4].y += xs*w.y;
                    acc[o4].z += xs*w.z; acc[o4].w += xs*w.w;
                }
            }
        }
    }
    float4* outp = (float4*)(g_xt + (size_t)(g*NRr + r)*OC);
    #pragma unroll
    for (int o4 = 0; o4 < 16; o4++) outp[o4] = acc[o4];
}

// Deterministic per-graph CSR build, counting-sort style, all 8 warps active.
// Bucket order = ascending edge id (stable), matching XLA scatter order.
__global__ void __launch_bounds__(256) k_csr(const int* __restrict__ ei,
                                             const float* __restrict__ eattr) {
    __shared__ unsigned short ldst[EPG];    // local dst per edge (17 KB)
    __shared__ unsigned short lpos[EPG];    // bucket slot per edge (17 KB)
    __shared__ int cw[8][NRr];              // per-warp histogram -> per-warp base (8.6 KB)
    __shared__ int tot[NRr], off[NRr];
    int g = blockIdx.x, tid = threadIdx.x;
    int lane = tid & 31, wid = tid >> 5;
    int base = g*EPG;
    int cbeg = wid*CHUNK;

    // stage local dsts; zero per-warp counters
    for (int i = tid; i < EPG; i += 256)
        ldst[i] = (unsigned short)(ei[ET + base + i] - g*NRr);
    for (int i = tid; i < 8*NRr; i += 256) ((int*)cw)[i] = 0;
    __syncthreads();

    // per-warp histogram over its own chunk (private row => no cross-warp races)
    for (int i = cbeg + lane; i < cbeg + CHUNK; i += 32)
        atomicAdd(&cw[wid][ldst[i]], 1);
    __syncthreads();

    // totals per bin
    for (int d = tid; d < NRr; d += 256) {
        int s = 0;
        #pragma unroll
        for (int w = 0; w < 8; w++) s += cw[w][d];
        tot[d] = s;
    }
    __syncthreads();

    // exclusive scan over 268 bins (warp 0)
    if (wid == 0) {
        int carry = 0;
        for (int c = 0; c < 9; c++) {
            int idx = c*32 + lane;
            int v = (idx < NRr) ? tot[idx] : 0;
            int incl = v;
            #pragma unroll
            for (int o = 1; o < 32; o <<= 1) {
                int t = __shfl_up_sync(0xffffffffu, incl, o);
                if (lane >= o) incl += t;
            }
            if (idx < NRr) off[idx] = incl - v + carry;
            carry += __shfl_sync(0xffffffffu, incl, 31);
        }
    }
    __syncthreads();

    // transform cw in place: cw[w][d] = off[d] + sum_{w'<w} cw[w'][d]
    for (int d = tid; d < NRr; d += 256) {
        int run = off[d];
        #pragma unroll
        for (int w = 0; w < 8; w++) { int t = cw[w][d]; cw[w][d] = run; run += t; }
        g_off[g*NRr + d] = base + off[d];
    }
    if (g == NB-1 && tid == 0) g_off[NT] = ET;
    __syncthreads();

    // stable ranking: each warp walks ITS chunk in ascending order (34 batches)
    for (int it = 0; it < (CHUNK + 31)/32; it++) {
        int idx = cbeg + it*32 + lane;
        bool valid = (idx < cbeg + CHUNK);
        int d = valid ? (int)ldst[idx] : (NRr + lane);   // invalid lanes: unique dummies
        unsigned mask = __match_any_sync(0xffffffffu, d);
        int rank = __popc(mask & ((1u << lane) - 1u));
        int leader = __ffs(mask) - 1;
        int prior = valid ? cw[wid][d] : 0;
        if (valid && lane == leader) cw[wid][d] = prior + __popc(mask);
        if (valid) lpos[idx] = (unsigned short)(prior + rank);
    }
    __syncthreads();

    // scatter (local src, ea) into bucket slots
    for (int i = tid; i < EPG; i += 256) {
        int pos = base + (int)lpos[i];
        g_bsrc[pos] = (unsigned short)(ei[base + i] - g*NRr);
        g_bea[pos]  = eattr[base + i];
    }
}

// Fused gather + self-loop + bias + ELU + LayerNorm.
// Block per graph: whole xt tile (268x64 = 68.6KB) staged in smem, so the
// E*256B of random src-row reads hit smem instead of L2.
// Deterministic: edge-id ascending sum order, self-loop last.
__global__ void __launch_bounds__(256) k_gather(const float* __restrict__ cbias,
                                                const float* __restrict__ gam,
                                                const float* __restrict__ bet) {
    extern __shared__ float tile[];         // NRr*OC floats
    int g = blockIdx.x;
    int w = threadIdx.x >> 5, lane = threadIdx.x & 31;

    const float4* srcx = (const float4*)(g_xt + (size_t)g*NRr*OC);
    float4* t4 = (float4*)tile;
    for (int i = threadIdx.x; i < NRr*OC/4; i += 256) t4[i] = srcx[i];
    __syncthreads();

    float2 bb = ((const float2*)cbias)[lane];
    float2 sg = ((const float2*)(g_tab + QT*OC))[lane];
    float2 gm = ((const float2*)gam)[lane];
    float2 bt = ((const float2*)bet)[lane];

    for (int dl = w; dl < NRr; dl += 8) {
        int n = g*NRr + dl;
        int o0 = g_off[n];
        int cnt = g_off[n+1] - o0;
        float2 acc = make_float2(0.f, 0.f);
        for (int jb = 0; jb < cnt; jb += 32) {
            int nj = min(32, cnt - jb);
            int myS = 0; float myE = 0.f;
            if (lane < nj) {
                myS = (int)g_bsrc[o0 + jb + lane];
                myE = g_bea [o0 + jb + lane];
            }
            for (int j = 0; j < nj; j++) {
                int   s  = __shfl_sync(0xffffffffu, myS, j);
                float ea = __shfl_sync(0xffffffffu, myE, j);
                float f = ea * (float)QT;
                int q = (int)f; if (q > QT-1) q = QT-1;
                float fr = f - (float)q;
                float2 t0 = ((const float2*)(g_tab + q*OC))[lane];
                float2 t1 = ((const float2*)(g_tab + q*OC + OC))[lane];
                float2 xv = ((const float2*)(tile + s*OC))[lane];
                acc.x += xv.x * (t0.x + (t1.x - t0.x)*fr);
                acc.y += xv.y * (t0.y + (t1.y - t0.y)*fr);
            }
        }
        // self-loop (appended last in reference), then bias
        float2 xn = ((const float2*)(tile + dl*OC))[lane];
        acc.x += xn.x * sg.x; acc.y += xn.y * sg.y;
        acc.x += bb.x;        acc.y += bb.y;
        // ELU
        acc.x = acc.x > 0.f ? acc.x : expm1f(acc.x);
        acc.y = acc.y > 0.f ? acc.y : expm1f(acc.y);
        // LayerNorm (warp reduce over 64 channels)
        float s1 = acc.x + acc.y;
        #pragma unroll
        for (int o = 16; o; o >>= 1) s1 += __shfl_xor_sync(0xffffffffu, s1, o);
        float mu = s1 * (1.f/64.f);
        float dx = acc.x - mu, dy = acc.y - mu;
        float s2 = dx*dx + dy*dy;
        #pragma unroll
        for (int o = 16; o; o >>= 1) s2 += __shfl_xor_sync(0xffffffffu, s2, o);
        float inv = 1.0f / sqrtf(s2*(1.f/64.f) + LN_EPS);
        float2 h;
        h.x = dx*inv*gm.x + bt.x;
        h.y = dy*inv*gm.y + bt.y;
        ((float2*)(g_out + (size_t)n*OC))[lane] = h;
    }
}

// attention scores: score[n] = tanh(h@W1+b1)@w2 + b2 ; written straight into d_out
__global__ void __launch_bounds__(256) k_score(const float* __restrict__ W1,
                                               const float* __restrict__ b1,
                                               const float* __restrict__ w2,
                                               const float* __restrict__ b2,
                                               float* __restrict__ dout) {
    __shared__ float W1s[OC*OC];
    __shared__ float b1s[OC];
    __shared__ float w2s[OC];
    for (int i = threadIdx.x; i < OC*OC; i += 256) W1s[i] = W1[i];
    if (threadIdx.x < OC) { b1s[threadIdx.x] = b1[threadIdx.x]; w2s[threadIdx.x] = w2[threadIdx.x]; }
    __syncthreads();
    int n = blockIdx.x*256 + threadIdx.x;
    if (n >= NT) return;
    float h[64];
    const float4* hr = (const float4*)(g_out + (size_t)n*OC);
    #pragma unroll
    for (int i = 0; i < 16; i++) {
        float4 t = hr[i];
        h[i*4+0]=t.x; h[i*4+1]=t.y; h[i*4+2]=t.z; h[i*4+3]=t.w;
    }
    float sc = b2[0];
    for (int o4 = 0; o4 < 16; o4++) {
        float4 u = ((const float4*)b1s)[o4];
        #pragma unroll 8
        for (int c = 0; c < 64; c++) {
            float hv = h[c];
            float4 w = ((const float4*)W1s)[c*16 + o4];
            u.x += hv*w.x; u.y += hv*w.y; u.z += hv*w.z; u.w += hv*w.w;
        }
        float4 w2v = ((const float4*)w2s)[o4];
        sc += tanhf(u.x)*w2v.x + tanhf(u.y)*w2v.y + tanhf(u.z)*w2v.z + tanhf(u.w)*w2v.w;
    }
    dout[SC_OFF + n] = sc;
}

// per-graph top-K via full bitonic sort (desc value, tie: asc index like jax top_k)
__global__ void __launch_bounds__(512) k_top(float* __restrict__ dout) {
    __shared__ float sv[512];
    __shared__ int   si[512];
    __shared__ float ssig[KK];
    int g = blockIdx.x, t = threadIdx.x;
    sv[t] = (t < NRr) ? dout[SC_OFF + g*NRr + t] : -3.402823466e+38f;
    si[t] = t;
    __syncthreads();
    for (int k = 2; k <= 512; k <<= 1) {
        for (int j = k >> 1; j > 0; j >>= 1) {
            int ixj = t ^ j;
            if (ixj > t) {
                float av = sv[t], bv = sv[ixj];
                int ai = si[t], bi = si[ixj];
                bool aFirst = (av > bv) || (av == bv && ai < bi);
                bool up = ((t & k) == 0);
                bool doswap = up ? (!aFirst) : aFirst;
                if (doswap) { sv[t] = bv; sv[ixj] = av; si[t] = bi; si[ixj] = ai; }
            }
            __syncthreads();
        }
    }
    for (int i = t; i < KK; i += 512) {
        float v = sv[i];
        ssig[i] = 1.f / (1.f + expf(-v));
        int li = si[i];
        dout[PERM_OFF + g*KK + i] = (float)(g*NRr + li);
        dout[BAT_OFF  + g*KK + i] = (float)g;
    }
    __syncthreads();
    for (int j = t; j < KK*OC; j += 512) {
        int i = j >> 6, c = j & 63;
        int li = si[i];
        dout[XP_OFF + (size_t)(g*KK + i)*OC + c] =
            g_out[((size_t)(g*NRr + li))*OC + c] * ssig[i];
    }
}

// ---------------- launch ---------------------------------------------------
extern "C" void kernel_launch(void* const* d_in, const int* in_sizes, int n_in,
                              void* d_out, int out_size) {
    const float* x      = (const float*)d_in[0];
    const int*   ei     = (const int*)  d_in[1];
    const float* eattr  = (const float*)d_in[2];
    // d_in[3] = batch (recomputed analytically)
    const float* basis  = (const float*)d_in[4];
    const float* roicom = (const float*)d_in[5];
    const float* ew_w   = (const float*)d_in[6];
    const float* ew_b   = (const float*)d_in[7];
    const float* cbias  = (const float*)d_in[8];
    const float* gam    = (const float*)d_in[9];
    const float* bet    = (const float*)d_in[10];
    const float* W1     = (const float*)d_in[11];
    const float* b1     = (const float*)d_in[12];
    const float* w2     = (const float*)d_in[13];
    const float* b2     = (const float*)d_in[14];
    float* dout = (float*)d_out;

    static int smem_set = 0;
    if (!smem_set) {
        cudaFuncSetAttribute(k_gather, cudaFuncAttributeMaxDynamicSharedMemorySize,
                             NRr*OC*(int)sizeof(float));
        smem_set = 1;
    }

    k_cw<<<1, NRr>>>(roicom);
    k_tab<<<QT+1, OC>>>(ew_w, ew_b);
    k_roik<<<NRr, 256>>>(basis);
    k_csr<<<NB, 256>>>(ei, eattr);
    k_xt<<<NRr, 256>>>(x);
    k_gather<<<NB, 256, NRr*OC*sizeof(float)>>>(cbias, gam, bet);
    k_score<<<(NT + 255)/256, 256>>>(W1, b1, w2, b2, dout);
    k_top<<<NB, 512>>>(dout);
}

// round 7
// speedup vs baseline: 1.3909x; 1.3909x over previous
#include <cuda_runtime.h>
#include <math.h>

#define NB   256            // graphs
#define NRr  268            // ROIs per graph
#define NT   (NB*NRr)       // total nodes = 68608
#define IC   256
#define OC   64
#define NCm  7
#define DEG  32
#define EPG  (NRr*DEG)      // edges per graph = 8576
#define ET   (NT*DEG)       // total edges = 2195456
#define KK   214            // top-k per graph
#define QT   256            // sigmoid table resolution
#define LN_EPS 1e-5f
#define CHUNK (EPG/8)       // 1072 edges per warp in k_csr

// output layout (float32, concatenated in reference return order)
#define XP_OFF   0
#define BAT_OFF  (NB*KK*OC)                 // 3506176
#define SC_OFF   (BAT_OFF + NB*KK)          // 3560960
#define PERM_OFF (SC_OFF + NT)              // 3629568

// ---------------- scratch (device globals; no allocation allowed) ----------
__device__ float g_tab[(QT+1)*OC];          // sigmoid(ea*w[c]+b[c]) table, row QT = self-loop gate
__device__ float g_roik[NRr*IC*OC];         // 17.6 MB
__device__ float g_xt[NT*OC];               // xt (per-node transform result)
__device__ float g_out[NT*OC];              // h after fused conv+ELU+LN
__device__ int   g_bsrc[ET];                // CSR bucket: global src node per slot
__device__ float g_bea[ET];                 // CSR bucket: edge_attr per slot
__device__ int   g_off[NT+1];               // CSR offsets (global edge space)

// ---------------- kernels --------------------------------------------------
__global__ void k_tab(const float* __restrict__ w, const float* __restrict__ b) {
    int q = blockIdx.x, c = threadIdx.x;
    double x = ((double)q / (double)QT) * (double)w[c] + (double)b[c];
    g_tab[q*OC + c] = (float)(1.0 / (1.0 + exp(-x)));
}

// mix basis kernels per ROI; community softmax computed in-block (fused k_cw)
__global__ void k_roik(const float* __restrict__ basis, const float* __restrict__ rc) {
    __shared__ float cws[NCm];
    int r = blockIdx.x;
    if (threadIdx.x == 0) {
        double v[NCm]; double m = -1e300;
        #pragma unroll
        for (int c = 0; c < NCm; c++) { v[c] = (double)rc[r*NCm + c]; if (v[c] > m) m = v[c]; }
        double s = 0.0;
        #pragma unroll
        for (int c = 0; c < NCm; c++) { v[c] = exp(v[c] - m); s += v[c]; }
        #pragma unroll
        for (int c = 0; c < NCm; c++) cws[c] = (float)(v[c] / s);
    }
    __syncthreads();
    float cwv[NCm];
    #pragma unroll
    for (int c = 0; c < NCm; c++) cwv[c] = cws[c];
    const float4* b4 = (const float4*)basis;
    float4* o4 = (float4*)(g_roik + (size_t)r*IC*OC);
    for (int idx = threadIdx.x; idx < IC*OC/4; idx += 256) {
        float4 acc = make_float4(0.f,0.f,0.f,0.f);
        #pragma unroll
        for (int c = 0; c < NCm; c++) {
            float4 t = b4[c*(IC*OC/4) + idx];
            acc.x += cwv[c]*t.x; acc.y += cwv[c]*t.y;
            acc.z += cwv[c]*t.z; acc.w += cwv[c]*t.w;
        }
        o4[idx] = acc;
    }
}

// grouped GEMM: block = ROI r, thread = graph g. xt[g*NRr+r,:] = x[row,:] @ roik[r]
__global__ void __launch_bounds__(256) k_xt(const float* __restrict__ x) {
    __shared__ float Ws[64*OC];             // 16 KB K-tile of W
    int r = blockIdx.x, g = threadIdx.x;
    float4 acc[16];
    #pragma unroll
    for (int i = 0; i < 16; i++) acc[i] = make_float4(0.f,0.f,0.f,0.f);
    const float* xrow = x + ((size_t)(g*NRr + r))*IC;
    for (int kt = 0; kt < 4; kt++) {
        __syncthreads();
        const float4* src = (const float4*)(g_roik + (size_t)r*IC*OC + (size_t)kt*64*OC);
        float4* dst = (float4*)Ws;
        for (int i = threadIdx.x; i < 64*OC/4; i += 256) dst[i] = src[i];
        __syncthreads();
        const float4* xr4 = (const float4*)(xrow + kt*64);
        for (int k4 = 0; k4 < 16; k4++) {
            float4 xv = xr4[k4];
            #pragma unroll
            for (int kk = 0; kk < 4; kk++) {
                float xs = (&xv.x)[kk];
                const float4* wrow = (const float4*)(Ws + (k4*4 + kk)*OC);
                #pragma unroll
                for (int o4 = 0; o4 < 16; o4++) {
                    float4 w = wrow[o4];
                    acc[o4].x += xs*w.x; acc[o4].y += xs*w.y;
                    acc[o4].z += xs*w.z; acc[o4].w += xs*w.w;
                }
            }
        }
    }
    float4* outp = (float4*)(g_xt + (size_t)(g*NRr + r)*OC);
    #pragma unroll
    for (int o4 = 0; o4 < 16; o4++) outp[o4] = acc[o4];
}

// Deterministic per-graph CSR build, counting-sort style, all 8 warps active.
// Bucket order = ascending edge id (stable), matching XLA scatter order.
__global__ void __launch_bounds__(256) k_csr(const int* __restrict__ ei,
                                             const float* __restrict__ eattr) {
    __shared__ unsigned short ldst[EPG];    // local dst per edge (17 KB)
    __shared__ unsigned short lpos[EPG];    // bucket slot per edge (17 KB)
    __shared__ int cw[8][NRr];              // per-warp histogram -> per-warp base (8.6 KB)
    __shared__ int tot[NRr], off[NRr];
    int g = blockIdx.x, tid = threadIdx.x;
    int lane = tid & 31, wid = tid >> 5;
    int base = g*EPG;
    int cbeg = wid*CHUNK;

    // stage local dsts; zero per-warp counters
    for (int i = tid; i < EPG; i += 256)
        ldst[i] = (unsigned short)(ei[ET + base + i] - g*NRr);
    for (int i = tid; i < 8*NRr; i += 256) ((int*)cw)[i] = 0;
    __syncthreads();

    // per-warp histogram over its own chunk (private row => no cross-warp races)
    for (int i = cbeg + lane; i < cbeg + CHUNK; i += 32)
        atomicAdd(&cw[wid][ldst[i]], 1);
    __syncthreads();

    // totals per bin
    for (int d = tid; d < NRr; d += 256) {
        int s = 0;
        #pragma unroll
        for (int w = 0; w < 8; w++) s += cw[w][d];
        tot[d] = s;
    }
    __syncthreads();

    // exclusive scan over 268 bins (warp 0)
    if (wid == 0) {
        int carry = 0;
        for (int c = 0; c < 9; c++) {
            int idx = c*32 + lane;
            int v = (idx < NRr) ? tot[idx] : 0;
            int incl = v;
            #pragma unroll
            for (int o = 1; o < 32; o <<= 1) {
                int t = __shfl_up_sync(0xffffffffu, incl, o);
                if (lane >= o) incl += t;
            }
            if (idx < NRr) off[idx] = incl - v + carry;
            carry += __shfl_sync(0xffffffffu, incl, 31);
        }
    }
    __syncthreads();

    // transform cw in place: cw[w][d] = off[d] + sum_{w'<w} cw[w'][d]
    for (int d = tid; d < NRr; d += 256) {
        int run = off[d];
        #pragma unroll
        for (int w = 0; w < 8; w++) { int t = cw[w][d]; cw[w][d] = run; run += t; }
        g_off[g*NRr + d] = base + off[d];
    }
    if (g == NB-1 && tid == 0) g_off[NT] = ET;
    __syncthreads();

    // stable ranking: each warp walks ITS chunk in ascending order (34 batches)
    for (int it = 0; it < (CHUNK + 31)/32; it++) {
        int idx = cbeg + it*32 + lane;
        bool valid = (idx < cbeg + CHUNK);
        int d = valid ? (int)ldst[idx] : (NRr + lane);   // invalid lanes: unique dummies
        unsigned mask = __match_any_sync(0xffffffffu, d);
        int rank = __popc(mask & ((1u << lane) - 1u));
        int leader = __ffs(mask) - 1;
        int prior = valid ? cw[wid][d] : 0;
        if (valid && lane == leader) cw[wid][d] = prior + __popc(mask);
        if (valid) lpos[idx] = (unsigned short)(prior + rank);
    }
    __syncthreads();

    // scatter (global src, ea) into bucket slots
    for (int i = tid; i < EPG; i += 256) {
        int pos = base + (int)lpos[i];
        g_bsrc[pos] = ei[base + i];
        g_bea[pos]  = eattr[base + i];
    }
}

// Fused gather + self-loop + bias + ELU + LayerNorm. Warp per dst node.
// Deterministic: fixed (edge-id ascending) summation order, self-loop last.
__global__ void __launch_bounds__(256) k_gather(const float* __restrict__ cbias,
                                                const float* __restrict__ gam,
                                                const float* __restrict__ bet) {
    __shared__ int   s_s[8][128];
    __shared__ float s_e[8][128];
    int w = threadIdx.x >> 5, lane = threadIdx.x & 31;
    int n = blockIdx.x*8 + w;
    int o0 = g_off[n];
    int cnt = g_off[n+1] - o0;
    if (cnt > 128) cnt = 128;               // statistically impossible (mean 32)
    for (int j = lane; j < cnt; j += 32) {
        s_s[w][j] = g_bsrc[o0 + j];
        s_e[w][j] = g_bea [o0 + j];
    }
    __syncwarp();
    float2 acc = make_float2(0.f, 0.f);
    #pragma unroll 4
    for (int j = 0; j < cnt; j++) {
        int s = s_s[w][j];
        float ea = s_e[w][j];
        float f = ea * (float)QT;
        int q = (int)f; if (q > QT-1) q = QT-1;
        float fr = f - (float)q;
        float2 t0 = ((const float2*)(g_tab + q*OC))[lane];
        float2 t1 = ((const float2*)(g_tab + q*OC + OC))[lane];
        float2 xv = ((const float2*)(g_xt + (size_t)s*OC))[lane];
        acc.x += xv.x * (t0.x + (t1.x - t0.x)*fr);
        acc.y += xv.y * (t0.y + (t1.y - t0.y)*fr);
    }
    // self-loop (appended last in reference), then bias
    float2 sg = ((const float2*)(g_tab + QT*OC))[lane];
    float2 xn = ((const float2*)(g_xt + (size_t)n*OC))[lane];
    acc.x += xn.x * sg.x; acc.y += xn.y * sg.y;
    float2 bb = ((const float2*)cbias)[lane];
    acc.x += bb.x; acc.y += bb.y;
    // ELU
    acc.x = acc.x > 0.f ? acc.x : expm1f(acc.x);
    acc.y = acc.y > 0.f ? acc.y : expm1f(acc.y);
    // LayerNorm (warp reduce over 64 channels)
    float s1 = acc.x + acc.y;
    #pragma unroll
    for (int o = 16; o; o >>= 1) s1 += __shfl_xor_sync(0xffffffffu, s1, o);
    float mu = s1 * (1.f/64.f);
    float dx = acc.x - mu, dy = acc.y - mu;
    float s2 = dx*dx + dy*dy;
    #pragma unroll
    for (int o = 16; o; o >>= 1) s2 += __shfl_xor_sync(0xffffffffu, s2, o);
    float inv = 1.0f / sqrtf(s2*(1.f/64.f) + LN_EPS);
    float2 gm = ((const float2*)gam)[lane];
    float2 bt = ((const float2*)bet)[lane];
    float2 h;
    h.x = dx*inv*gm.x + bt.x;
    h.y = dy*inv*gm.y + bt.y;
    ((float2*)(g_out + (size_t)n*OC))[lane] = h;
}

// attention scores: score[n] = tanh(h@W1+b1)@w2 + b2 ; written straight into d_out
__global__ void __launch_bounds__(256) k_score(const float* __restrict__ W1,
                                               const float* __restrict__ b1,
                                               const float* __restrict__ w2,
                                               const float* __restrict__ b2,
                                               float* __restrict__ dout) {
    __shared__ float W1s[OC*OC];
    __shared__ float b1s[OC];
    __shared__ float w2s[OC];
    for (int i = threadIdx.x; i < OC*OC; i += 256) W1s[i] = W1[i];
    if (threadIdx.x < OC) { b1s[threadIdx.x] = b1[threadIdx.x]; w2s[threadIdx.x] = w2[threadIdx.x]; }
    __syncthreads();
    int n = blockIdx.x*256 + threadIdx.x;
    if (n >= NT) return;
    float h[64];
    const float4* hr = (const float4*)(g_out + (size_t)n*OC);
    #pragma unroll
    for (int i = 0; i < 16; i++) {
        float4 t = hr[i];
        h[i*4+0]=t.x; h[i*4+1]=t.y; h[i*4+2]=t.z; h[i*4+3]=t.w;
    }
    float sc = b2[0];
    for (int o4 = 0; o4 < 16; o4++) {
        float4 u = ((const float4*)b1s)[o4];
        #pragma unroll 8
        for (int c = 0; c < 64; c++) {
            float hv = h[c];
            float4 w = ((const float4*)W1s)[c*16 + o4];
            u.x += hv*w.x; u.y += hv*w.y; u.z += hv*w.z; u.w += hv*w.w;
        }
        float4 w2v = ((const float4*)w2s)[o4];
        sc += tanhf(u.x)*w2v.x + tanhf(u.y)*w2v.y + tanhf(u.z)*w2v.z + tanhf(u.w)*w2v.w;
    }
    dout[SC_OFF + n] = sc;
}

// per-graph top-K via full bitonic sort (desc value, tie: asc index like jax top_k)
__global__ void __launch_bounds__(512) k_top(float* __restrict__ dout) {
    __shared__ float sv[512];
    __shared__ int   si[512];
    __shared__ float ssig[KK];
    int g = blockIdx.x, t = threadIdx.x;
    sv[t] = (t < NRr) ? dout[SC_OFF + g*NRr + t] : -3.402823466e+38f;
    si[t] = t;
    __syncthreads();
    for (int k = 2; k <= 512; k <<= 1) {
        for (int j = k >> 1; j > 0; j >>= 1) {
            int ixj = t ^ j;
            if (ixj > t) {
                float av = sv[t], bv = sv[ixj];
                int ai = si[t], bi = si[ixj];
                bool aFirst = (av > bv) || (av == bv && ai < bi);
                bool up = ((t & k) == 0);
                bool doswap = up ? (!aFirst) : aFirst;
                if (doswap) { sv[t] = bv; sv[ixj] = av; si[t] = bi; si[ixj] = ai; }
            }
            __syncthreads();
        }
    }
    for (int i = t; i < KK; i += 512) {
        float v = sv[i];
        ssig[i] = 1.f / (1.f + expf(-v));
        int li = si[i];
        dout[PERM_OFF + g*KK + i] = (float)(g*NRr + li);
        dout[BAT_OFF  + g*KK + i] = (float)g;
    }
    __syncthreads();
    for (int j = t; j < KK*OC; j += 512) {
        int i = j >> 6, c = j & 63;
        int li = si[i];
        dout[XP_OFF + (size_t)(g*KK + i)*OC + c] =
            g_out[((size_t)(g*NRr + li))*OC + c] * ssig[i];
    }
}

// ---------------- launch ---------------------------------------------------
extern "C" void kernel_launch(void* const* d_in, const int* in_sizes, int n_in,
                              void* d_out, int out_size) {
    const float* x      = (const float*)d_in[0];
    const int*   ei     = (const int*)  d_in[1];
    const float* eattr  = (const float*)d_in[2];
    // d_in[3] = batch (recomputed analytically)
    const float* basis  = (const float*)d_in[4];
    const float* roicom = (const float*)d_in[5];
    const float* ew_w   = (const float*)d_in[6];
    const float* ew_b   = (const float*)d_in[7];
    const float* cbias  = (const float*)d_in[8];
    const float* gam    = (const float*)d_in[9];
    const float* bet    = (const float*)d_in[10];
    const float* W1     = (const float*)d_in[11];
    const float* b1     = (const float*)d_in[12];
    const float* w2     = (const float*)d_in[13];
    const float* b2     = (const float*)d_in[14];
    float* dout = (float*)d_out;

    static cudaStream_t s1 = (cudaStream_t)0;
    static cudaEvent_t  e0 = (cudaEvent_t)0, e1 = (cudaEvent_t)0;
    if (!s1) {
        cudaStreamCreateWithFlags(&s1, cudaStreamNonBlocking);
        cudaEventCreateWithFlags(&e0, cudaEventDisableTiming);
        cudaEventCreateWithFlags(&e1, cudaEventDisableTiming);
    }

    // fork: side stream builds the CSR + gate table while main stream does GEMMs
    cudaEventRecord(e0, 0);
    cudaStreamWaitEvent(s1, e0, 0);
    k_tab<<<QT+1, OC, 0, s1>>>(ew_w, ew_b);
    k_csr<<<NB, 256, 0, s1>>>(ei, eattr);
    cudaEventRecord(e1, s1);

    // main stream: roik (fused softmax) -> xt
    k_roik<<<NRr, 256>>>(basis, roicom);
    k_xt<<<NRr, 256>>>(x);

    // join, then gather -> score -> top
    cudaStreamWaitEvent(0, e1, 0);
    k_gather<<<NT/8, 256>>>(cbias, gam, bet);
    k_score<<<(NT + 255)/256, 256>>>(W1, b1, w2, b2, dout);
    k_top<<<NB, 512>>>(dout);
}